// round 9
// baseline (speedup 1.0000x reference)
#include <cuda_runtime.h>

#define NPTS  16384
#define KNN_K 16
#define QB    64

// edge_mlp smem offsets (weights swizzled-transposed, pitch 64)
#define O_WB   0
#define O_W1A  4096
#define O_W2A  8192
#define O_W2B  12288
#define O_W3A  16384
#define O_W3B  20480
#define O_W3C  24576
#define O_F    28672
#define O_H1   32768
#define O_H2   36864
#define O_H3   40960
#define O_H4   45056
#define O_C    49152
#define SMEM_FLOATS 50176

__device__ __align__(16) int   g_knn[NPTS * KNN_K];
__device__ __align__(16) float g_const[NPTS * 256];

static __device__ __forceinline__ unsigned long long pack2(float a, float b) {
    unsigned long long r;
    asm("mov.b64 %0, {%1, %2};" : "=l"(r) : "f"(a), "f"(b));
    return r;
}
static __device__ __forceinline__ void unpack2(unsigned long long v, float &a, float &b) {
    asm("mov.b64 {%0, %1}, %2;" : "=f"(a), "=f"(b) : "l"(v));
}
static __device__ __forceinline__ void ffma2(unsigned long long &d, unsigned long long a, unsigned long long b) {
    asm("fma.rn.f32x2 %0, %1, %2, %0;" : "+l"(d) : "l"(a), "l"(b));
}

// ================= KNN (round-2 proven version, verbatim) =================
static __device__ __forceinline__ void warp_scan_find(const unsigned* __restrict__ h, unsigned target,
                                                      unsigned* outB, unsigned* outCb) {
    int lane = threadIdx.x & 31;
    unsigned loc[8], s = 0;
#pragma unroll
    for (int j = 0; j < 8; j++) { loc[j] = h[lane * 8 + j]; s += loc[j]; }
    unsigned pre = s;
#pragma unroll
    for (int o = 1; o < 32; o <<= 1) {
        unsigned v = __shfl_up_sync(0xffffffffu, pre, o);
        if (lane >= o) pre += v;
    }
    unsigned excl = pre - s;
    bool mine = (excl < target) && (excl + s >= target);
    unsigned mb = __ballot_sync(0xffffffffu, mine);
    int lead = __ffs(mb) - 1;
    if (lane == lead) {
        unsigned run = excl, B = 0, cbv = 0;
        bool done = false;
#pragma unroll
        for (int j = 0; j < 8; j++) {
            if (!done && run + loc[j] >= target) { B = lane * 8 + j; cbv = run; done = true; }
            run += loc[j];
        }
        *outB = B; *outCb = cbv;
    }
}

__global__ void __launch_bounds__(256, 2) knn_kernel(const float* __restrict__ pos) {
    extern __shared__ char smraw[];
    float4*   tile  = (float4*)smraw;
    unsigned* keys  = (unsigned*)(smraw + 65536);
    unsigned* hist  = (unsigned*)(smraw + 81920);
    unsigned* hist2 = (unsigned*)(smraw + 82944);
    unsigned* bufK  = (unsigned*)(smraw + 83968);
    int*      bufI  = (int*)(smraw + 84480);
    unsigned* sv    = (unsigned*)(smraw + 84992);

    int t = threadIdx.x;
    int lane = t & 31;
    int b = blockIdx.x >> 6;
    int qoff = (blockIdx.x & 63) * QB;
    const float* P = pos + ((size_t)(b << 12)) * 3;
    for (int i = t; i < 4096; i += 256) {
        float px = P[3 * i], py = P[3 * i + 1], pz = P[3 * i + 2];
        tile[i] = make_float4(px, py, pz, px * px + py * py + pz * pz);
    }
    __syncthreads();

    for (int qi = 0; qi < QB; qi++) {
        int ql = qoff + qi;
        float4 qp = tile[ql];
        float qx = qp.x, qy = qp.y, qz = qp.z, qs = qp.w;
        hist[t] = 0; hist2[t] = 0;
        if (t == 0) sv[3] = 0;
        __syncthreads();

#pragma unroll 4
        for (int i = 0; i < 16; i++) {
            int c = t + (i << 8);
            float4 pc = tile[c];
            float d2 = qs + pc.w - 2.0f * (qx * pc.x + qy * pc.y + qz * pc.z);
            unsigned kb = __float_as_uint(d2);
            kb ^= ((unsigned)((int)kb >> 31)) | 0x80000000u;
            keys[c] = kb;
            unsigned bin = kb >> 24;
            unsigned m = __match_any_sync(0xffffffffu, bin);
            if (lane == __ffs(m) - 1) atomicAdd(&hist[bin], (unsigned)__popc(m));
        }
        __syncthreads();
        if (t < 32) warp_scan_find(hist, 17u, sv + 0, sv + 1);
        __syncthreads();
        unsigned B = sv[0], cb = sv[1];

#pragma unroll 4
        for (int i = 0; i < 16; i++) {
            int c = t + (i << 8);
            unsigned key = keys[c];
            unsigned b2 = ((key >> 24) == B) ? ((key >> 16) & 255u) : 0xffffffffu;
            unsigned m = __match_any_sync(0xffffffffu, b2);
            if (b2 != 0xffffffffu && lane == __ffs(m) - 1) atomicAdd(&hist2[b2], (unsigned)__popc(m));
        }
        __syncthreads();
        if (t < 32) warp_scan_find(hist2, 17u - cb, sv + 2, sv + 1);
        __syncthreads();
        unsigned cut = (B << 8) | sv[2];

#pragma unroll 4
        for (int i = 0; i < 16; i++) {
            int c = t + (i << 8);
            unsigned key = keys[c];
            if ((key >> 16) <= cut) {
                unsigned p = atomicAdd(&sv[3], 1u);
                if (p < 128u) { bufK[p] = key; bufI[p] = c; }
            }
        }
        __syncthreads();

        int M = min(sv[3], 128u);
        if (t < M) {
            unsigned mk = bufK[t]; int mi = bufI[t];
            int r = 0;
            for (int j = 0; j < M; j++) {
                unsigned ok = bufK[j]; int oi = bufI[j];
                if (ok < mk || (ok == mk && oi < mi)) r++;
            }
            if (r >= 1 && r <= 16) {
                int qg = (b << 12) + ql;
                g_knn[qg * KNN_K + (r - 1)] = mi;
            }
        }
        __syncthreads();
    }
}

// ================= per-point constants =================
__global__ void const_kernel(const float* __restrict__ x,
                             const float* __restrict__ Wf,  const float* __restrict__ bf,
                             const float* __restrict__ Wm1, const float* __restrict__ bm1,
                             const float* __restrict__ Wm2, const float* __restrict__ bm2,
                             const float* __restrict__ Wl,  const float* __restrict__ bl) {
    extern __shared__ float sm[];
    float* Wc   = sm;
    float* bias = sm + 64 * 256;
    float* xs   = bias + 256;
    int t = threadIdx.x;
    for (int i = t; i < 64 * 256; i += 256) {
        int d = i >> 8, j = i & 255;
        float v;
        if (j < 64)       v = Wf[d * 64 + j] - Wf[(128 + d) * 64 + j];
        else if (j < 128) v = Wm1[(64 + d) * 64 + (j - 64)];
        else if (j < 192) v = Wm2[(128 + d) * 64 + (j - 128)];
        else              v = Wl[(192 + d) * 64 + (j - 192)];
        Wc[i] = v;
    }
    bias[t] = (t < 64) ? bf[t] : (t < 128) ? bm1[t - 64] : (t < 192) ? bm2[t - 128] : bl[t - 192];

    for (int pt = blockIdx.x; pt < NPTS; pt += gridDim.x) {
        __syncthreads();
        if (t < 64) xs[t] = x[(size_t)pt * 64 + t];
        __syncthreads();
        float acc = bias[t];
#pragma unroll 8
        for (int d = 0; d < 64; d++) acc = fmaf(xs[d], Wc[d * 256 + t], acc);
        g_const[(size_t)pt * 256 + t] = acc;
    }
}

// ===== fused edge-MLP + max: 128 threads, 2 k-slots/thread, even/odd f32x2 =====
// weight (j,d) at woff + j*64 + sw(d); w loaded at ds=sw(d4) -> contents W[d4..d4+3]; h at plain d4.
__global__ void __launch_bounds__(128, 1)
edge_mlp_kernel(const float* __restrict__ x,
                const float* __restrict__ Wf, const float* __restrict__ Wm1,
                const float* __restrict__ Wm2, const float* __restrict__ Wl,
                float* __restrict__ out) {
    extern __shared__ float sm[];
    int t = threadIdx.x;

    for (int i = t; i < 4096; i += 128) {
        int d = i >> 6, j = i & 63;
        int o = j * 64 + ((((d >> 2) ^ ((j >> 2) & 7))) << 2) + (d & 3);
        sm[O_WB  + o] = Wf[(64 + d) * 64 + j] + Wf[(128 + d) * 64 + j];
        sm[O_W1A + o] = Wm1[i];
        sm[O_W2A + o] = Wm2[i];
        sm[O_W2B + o] = Wm2[4096 + i];
        sm[O_W3A + o] = Wl[i];
        sm[O_W3B + o] = Wl[4096 + i];
        sm[O_W3C + o] = Wl[8192 + i];
    }
    __syncthreads();

    const int kk  = t >> 4;          // k-slot base: k = kk and kk+8
    const int jb  = (t & 15) << 2;   // output column base
    const int key = (jb >> 2) & 7;   // swizzle key
    unsigned long long a[2][4][4];   // [kslot][p][col] = (even-d sum, odd-d sum)

    for (int grp = blockIdx.x; grp < NPTS / 4; grp += gridDim.x) {
        int base = grp * 4;
        int b = base >> 12;
        {   // gather knn feats [p][k][64] + constants (128 threads)
            int r = t >> 1, half = t & 1;
            int nb = g_knn[grp * 64 + r];
            const float4* src = (const float4*)(x + ((size_t)(b << 12) + nb) * 64) + half * 8;
            float4* dst = (float4*)(sm + O_F + (r << 6)) + half * 8;
#pragma unroll
            for (int u = 0; u < 8; u++) dst[u] = src[u];
            ((float4*)(sm + O_C))[t]       = ((const float4*)(g_const + (size_t)grp * 1024))[t];
            ((float4*)(sm + O_C))[t + 128] = ((const float4*)(g_const + (size_t)grp * 1024))[t + 128];
        }
        __syncthreads();

        auto init_acc = [&](int coff) {
#pragma unroll
            for (int s = 0; s < 2; s++)
#pragma unroll
                for (int p = 0; p < 4; p++)
#pragma unroll
                    for (int j = 0; j < 4; j++)
                        a[s][p][j] = pack2(sm[O_C + (p << 8) + coff + jb + j], 0.0f);
        };
        // h layout [k][p][64]
        auto accum = [&](int hoff, int woff) {
            const float* hb0 = sm + hoff + (kk << 8);
            const float* hb1 = sm + hoff + ((kk + 8) << 8);
            const float* wp  = sm + woff + (jb << 6);
#pragma unroll 4
            for (int d4 = 0; d4 < 64; d4 += 4) {
                int ds = (((d4 >> 2) ^ key) << 2);
                ulonglong2 w0 = *(const ulonglong2*)(wp +       ds);
                ulonglong2 w1 = *(const ulonglong2*)(wp +  64 + ds);
                ulonglong2 w2 = *(const ulonglong2*)(wp + 128 + ds);
                ulonglong2 w3 = *(const ulonglong2*)(wp + 192 + ds);
#pragma unroll
                for (int s = 0; s < 2; s++) {
                    const float* hb = s ? hb1 : hb0;
                    ulonglong2 h0 = *(const ulonglong2*)(hb +       d4);
                    ulonglong2 h1 = *(const ulonglong2*)(hb +  64 + d4);
                    ulonglong2 h2 = *(const ulonglong2*)(hb + 128 + d4);
                    ulonglong2 h3 = *(const ulonglong2*)(hb + 192 + d4);
                    ffma2(a[s][0][0], h0.x, w0.x); ffma2(a[s][0][1], h0.x, w1.x); ffma2(a[s][0][2], h0.x, w2.x); ffma2(a[s][0][3], h0.x, w3.x);
                    ffma2(a[s][1][0], h1.x, w0.x); ffma2(a[s][1][1], h1.x, w1.x); ffma2(a[s][1][2], h1.x, w2.x); ffma2(a[s][1][3], h1.x, w3.x);
                    ffma2(a[s][2][0], h2.x, w0.x); ffma2(a[s][2][1], h2.x, w1.x); ffma2(a[s][2][2], h2.x, w2.x); ffma2(a[s][2][3], h2.x, w3.x);
                    ffma2(a[s][3][0], h3.x, w0.x); ffma2(a[s][3][1], h3.x, w1.x); ffma2(a[s][3][2], h3.x, w2.x); ffma2(a[s][3][3], h3.x, w3.x);
                    ffma2(a[s][0][0], h0.y, w0.y); ffma2(a[s][0][1], h0.y, w1.y); ffma2(a[s][0][2], h0.y, w2.y); ffma2(a[s][0][3], h0.y, w3.y);
                    ffma2(a[s][1][0], h1.y, w0.y); ffma2(a[s][1][1], h1.y, w1.y); ffma2(a[s][1][2], h1.y, w2.y); ffma2(a[s][1][3], h1.y, w3.y);
                    ffma2(a[s][2][0], h2.y, w0.y); ffma2(a[s][2][1], h2.y, w1.y); ffma2(a[s][2][2], h2.y, w2.y); ffma2(a[s][2][3], h2.y, w3.y);
                    ffma2(a[s][3][0], h3.y, w0.y); ffma2(a[s][3][1], h3.y, w1.y); ffma2(a[s][3][2], h3.y, w2.y); ffma2(a[s][3][3], h3.y, w3.y);
                }
            }
        };
        // layer-1 input F is [p][k][64]
        auto accum_f = [&](int woff) {
            const float* f0 = sm + O_F + (kk << 6);
            const float* f1 = sm + O_F + ((kk + 8) << 6);
            const float* wp = sm + woff + (jb << 6);
#pragma unroll 4
            for (int d4 = 0; d4 < 64; d4 += 4) {
                int ds = (((d4 >> 2) ^ key) << 2);
                ulonglong2 w0 = *(const ulonglong2*)(wp +       ds);
                ulonglong2 w1 = *(const ulonglong2*)(wp +  64 + ds);
                ulonglong2 w2 = *(const ulonglong2*)(wp + 128 + ds);
                ulonglong2 w3 = *(const ulonglong2*)(wp + 192 + ds);
#pragma unroll
                for (int s = 0; s < 2; s++) {
                    const float* fb = s ? f1 : f0;
                    ulonglong2 h0 = *(const ulonglong2*)(fb +        d4);
                    ulonglong2 h1 = *(const ulonglong2*)(fb + 1024 + d4);
                    ulonglong2 h2 = *(const ulonglong2*)(fb + 2048 + d4);
                    ulonglong2 h3 = *(const ulonglong2*)(fb + 3072 + d4);
                    ffma2(a[s][0][0], h0.x, w0.x); ffma2(a[s][0][1], h0.x, w1.x); ffma2(a[s][0][2], h0.x, w2.x); ffma2(a[s][0][3], h0.x, w3.x);
                    ffma2(a[s][1][0], h1.x, w0.x); ffma2(a[s][1][1], h1.x, w1.x); ffma2(a[s][1][2], h1.x, w2.x); ffma2(a[s][1][3], h1.x, w3.x);
                    ffma2(a[s][2][0], h2.x, w0.x); ffma2(a[s][2][1], h2.x, w1.x); ffma2(a[s][2][2], h2.x, w2.x); ffma2(a[s][2][3], h2.x, w3.x);
                    ffma2(a[s][3][0], h3.x, w0.x); ffma2(a[s][3][1], h3.x, w1.x); ffma2(a[s][3][2], h3.x, w2.x); ffma2(a[s][3][3], h3.x, w3.x);
                    ffma2(a[s][0][0], h0.y, w0.y); ffma2(a[s][0][1], h0.y, w1.y); ffma2(a[s][0][2], h0.y, w2.y); ffma2(a[s][0][3], h0.y, w3.y);
                    ffma2(a[s][1][0], h1.y, w0.y); ffma2(a[s][1][1], h1.y, w1.y); ffma2(a[s][1][2], h1.y, w2.y); ffma2(a[s][1][3], h1.y, w3.y);
                    ffma2(a[s][2][0], h2.y, w0.y); ffma2(a[s][2][1], h2.y, w1.y); ffma2(a[s][2][2], h2.y, w2.y); ffma2(a[s][2][3], h2.y, w3.y);
                    ffma2(a[s][3][0], h3.y, w0.y); ffma2(a[s][3][1], h3.y, w1.y); ffma2(a[s][3][2], h3.y, w2.y); ffma2(a[s][3][3], h3.y, w3.y);
                }
            }
        };
        auto store_h = [&](int hoff, bool relu) {
#pragma unroll
            for (int s = 0; s < 2; s++) {
                float* hb = sm + hoff + ((kk + s * 8) << 8);
#pragma unroll
                for (int p = 0; p < 4; p++) {
                    float v[4];
#pragma unroll
                    for (int j = 0; j < 4; j++) {
                        float e, o;
                        unpack2(a[s][p][j], e, o);
                        v[j] = e + o;
                        if (relu) v[j] = fmaxf(v[j], 0.0f);
                    }
                    *(float4*)(hb + (p << 6) + jb) = make_float4(v[0], v[1], v[2], v[3]);
                }
            }
        };

        init_acc(0);   accum_f(O_WB);                              store_h(O_H1, true);
        __syncthreads();
        init_acc(64);  accum(O_H1, O_W1A);                         store_h(O_H2, true);
        __syncthreads();
        init_acc(128); accum(O_H2, O_W2A); accum(O_H1, O_W2B);     store_h(O_H3, true);
        __syncthreads();
        init_acc(192); accum(O_H3, O_W3A); accum(O_H2, O_W3B); accum(O_H1, O_W3C);
        store_h(O_H4, false);
        __syncthreads();

        {   // max over K; h layout [k][p][64]; 128 threads -> 2 (p,j) pairs each
            int j = t & 63;
#pragma unroll
            for (int pi = 0; pi < 2; pi++) {
                int p = (t >> 6) + pi * 2;
                int pt = base + p;
                size_t orow = (size_t)pt * 320;
                float m4 = -3.4e38f, m3 = -3.4e38f, m2 = -3.4e38f, m1 = -3.4e38f;
#pragma unroll
                for (int kq = 0; kq < 16; kq++) {
                    int off = (kq << 8) + (p << 6) + j;
                    m1 = fmaxf(m1, sm[O_H1 + off]);
                    m2 = fmaxf(m2, sm[O_H2 + off]);
                    m3 = fmaxf(m3, sm[O_H3 + off]);
                    m4 = fmaxf(m4, sm[O_H4 + off]);
                }
                out[orow +       j] = m4;
                out[orow +  64 + j] = m3;
                out[orow + 128 + j] = m2;
                out[orow + 192 + j] = m1;
                out[orow + 256 + j] = x[(size_t)pt * 64 + j];
            }
        }
        __syncthreads();
    }
}

extern "C" void kernel_launch(void* const* d_in, const int* in_sizes, int n_in,
                              void* d_out, int out_size) {
    const float* x   = (const float*)d_in[0];
    const float* pos = (const float*)d_in[1];
    const float* Wf  = (const float*)d_in[2];
    const float* bf  = (const float*)d_in[3];
    const float* Wm1 = (const float*)d_in[4];
    const float* bm1 = (const float*)d_in[5];
    const float* Wm2 = (const float*)d_in[6];
    const float* bm2 = (const float*)d_in[7];
    const float* Wl  = (const float*)d_in[8];
    const float* bl  = (const float*)d_in[9];
    float* out = (float*)d_out;

    cudaFuncSetAttribute(knn_kernel, cudaFuncAttributeMaxDynamicSharedMemorySize, 85248);
    cudaFuncSetAttribute(const_kernel, cudaFuncAttributeMaxDynamicSharedMemorySize,
                         (64 * 256 + 256 + 64) * 4);
    cudaFuncSetAttribute(edge_mlp_kernel, cudaFuncAttributeMaxDynamicSharedMemorySize,
                         SMEM_FLOATS * 4);

    knn_kernel<<<256, 256, 85248>>>(pos);
    const_kernel<<<256, 256, (64 * 256 + 256 + 64) * 4>>>(x, Wf, bf, Wm1, bm1, Wm2, bm2, Wl, bl);
    edge_mlp_kernel<<<148, 128, SMEM_FLOATS * 4>>>(x, Wf, Wm1, Wm2, Wl, out);
}